// round 16
// baseline (speedup 1.0000x reference)
#include <cuda_runtime.h>
#include <cuda_bf16.h>
#include <cstdint>
#include <math.h>

typedef unsigned int u32;
typedef unsigned short u16;

#define NROWS 8192
#define DCOLS 1024
#define KDIM  8192
#define NITER 10

// tf32 GEMM (GEMM2): BK=32, dynamic smem (round-14 proven)
#define G2BK 32
#define G2AS_STRIDE 36
#define G2AS_STAGE (128 * G2AS_STRIDE)
#define G2BS_STRIDE 136
#define G2BS_STAGE (G2BK * G2BS_STRIDE)
#define GEMM2_DSMEM ((G2AS_STAGE + G2BS_STAGE) * 2 * 4)   // 71680 B

// bf16 GEMM (GEMM1): BK=64, 2-stage (round-15 proven, hoisted fragments)
#define HBK 64
#define HA_STRIDE 36
#define HA_STAGE (128 * HA_STRIDE)
#define HB_STRIDE 68
#define HB_STAGE (64 * HB_STRIDE)
#define GEMM1_DSMEM ((2 * HA_STAGE + 2 * HB_STAGE) * 4)   // 71680 B

// ---------------- scratch (static __device__, no allocation) ----------------
__device__ float g_support[(size_t)NROWS * DCOLS];
__device__ float g_posA[(size_t)NROWS * DCOLS];
__device__ float g_posB[(size_t)NROWS * DCOLS];
__device__ __nv_bfloat16 g_adj_bf[(size_t)NROWS * KDIM];
__device__ __nv_bfloat16 g_in_bf[(size_t)NROWS * DCOLS];
__device__ unsigned g_mm[2];
__device__ float4 g_draw[NITER * NROWS];                       // A, C, sp, mode
__device__ u16 g_ridx[(size_t)NITER * NROWS * DCOLS];          // 160 MB

struct KeyTab {
    u32 k[NITER][10];   // k1a,k1b,k2a,k2b,k3a,k3b,k4a,k4b,kba,kbb
};

// ---------------- threefry2x32 (JAX-exact) ----------------
__device__ __forceinline__ void dtf(u32 k0, u32 k1, u32 x0, u32 x1, u32& o0, u32& o1) {
    u32 ks2 = k0 ^ k1 ^ 0x1BD11BDAu;
    x0 += k0; x1 += k1;
#define TFROUND(r) { x0 += x1; x1 = __funnelshift_l(x1, x1, (r)); x1 ^= x0; }
    TFROUND(13) TFROUND(15) TFROUND(26) TFROUND(6)
    x0 += k1;  x1 += ks2 + 1u;
    TFROUND(17) TFROUND(29) TFROUND(16) TFROUND(24)
    x0 += ks2; x1 += k0 + 2u;
    TFROUND(13) TFROUND(15) TFROUND(26) TFROUND(6)
    x0 += k0;  x1 += k1 + 3u;
    TFROUND(17) TFROUND(29) TFROUND(16) TFROUND(24)
    x0 += k1;  x1 += ks2 + 4u;
    TFROUND(13) TFROUND(15) TFROUND(26) TFROUND(6)
    x0 += ks2; x1 += k0 + 5u;
#undef TFROUND
    o0 = x0; o1 = x1;
}

static void htf(u32 k0, u32 k1, u32 x0, u32 x1, u32* o0, u32* o1) {
    u32 ks[3] = {k0, k1, k0 ^ k1 ^ 0x1BD11BDAu};
    static const int R0[4] = {13, 15, 26, 6};
    static const int R1[4] = {17, 29, 16, 24};
    x0 += ks[0]; x1 += ks[1];
    for (int i = 0; i < 5; i++) {
        const int* R = (i & 1) ? R1 : R0;
        for (int j = 0; j < 4; j++) {
            x0 += x1;
            x1 = (x1 << R[j]) | (x1 >> (32 - R[j]));
            x1 ^= x0;
        }
        x0 += ks[(i + 1) % 3];
        x1 += ks[(i + 2) % 3] + (u32)(i + 1);
    }
    *o0 = x0; *o1 = x1;
}

__device__ __forceinline__ u32 dbits32(u32 k0, u32 k1, u32 e) {
    u32 o0, o1;
    dtf(k0, k1, 0u, e, o0, o1);
    return o0 ^ o1;
}
static u32 hbits32(u32 k0, u32 k1, u32 e) {
    u32 o0, o1;
    htf(k0, k1, 0u, e, &o0, &o1);
    return o0 ^ o1;
}

__device__ __forceinline__ float bits01(u32 b) {
    return __uint_as_float((b >> 9) | 0x3f800000u) - 1.0f;
}

__device__ __forceinline__ u32 f2key(float f) {
    u32 b = __float_as_uint(f);
    return (b & 0x80000000u) ? ~b : (b | 0x80000000u);
}
__device__ __forceinline__ float key2f(u32 k) {
    return __uint_as_float((k & 0x80000000u) ? (k ^ 0x80000000u) : ~k);
}

// ---------------- mma / cp.async helpers ----------------
__device__ __forceinline__ u32 f2tf32(float x) {
    u32 r;
    asm("cvt.rna.tf32.f32 %0, %1;" : "=r"(r) : "f"(x));
    return r;
}

__device__ __forceinline__ void mma_tf32(float* d, const u32* a, const u32* b) {
    asm volatile(
        "mma.sync.aligned.m16n8k8.row.col.f32.tf32.tf32.f32 "
        "{%0,%1,%2,%3}, {%4,%5,%6,%7}, {%8,%9}, {%0,%1,%2,%3};"
        : "+f"(d[0]), "+f"(d[1]), "+f"(d[2]), "+f"(d[3])
        : "r"(a[0]), "r"(a[1]), "r"(a[2]), "r"(a[3]), "r"(b[0]), "r"(b[1]));
}

__device__ __forceinline__ void mma_bf16(float* d, const u32* a, const u32* b) {
    asm volatile(
        "mma.sync.aligned.m16n8k16.row.col.f32.bf16.bf16.f32 "
        "{%0,%1,%2,%3}, {%4,%5,%6,%7}, {%8,%9}, {%0,%1,%2,%3};"
        : "+f"(d[0]), "+f"(d[1]), "+f"(d[2]), "+f"(d[3])
        : "r"(a[0]), "r"(a[1]), "r"(a[2]), "r"(a[3]), "r"(b[0]), "r"(b[1]));
}

__device__ __forceinline__ void ldsm_x4(u32* d, u32 saddr) {
    asm volatile(
        "ldmatrix.sync.aligned.m8n8.x4.shared.b16 {%0,%1,%2,%3}, [%4];"
        : "=r"(d[0]), "=r"(d[1]), "=r"(d[2]), "=r"(d[3]) : "r"(saddr));
}

__device__ __forceinline__ void ldsm_x4_trans(u32* d, u32 saddr) {
    asm volatile(
        "ldmatrix.sync.aligned.m8n8.x4.trans.shared.b16 {%0,%1,%2,%3}, [%4];"
        : "=r"(d[0]), "=r"(d[1]), "=r"(d[2]), "=r"(d[3]) : "r"(saddr));
}

__device__ __forceinline__ u32 smem_u32(const void* p) {
    return (u32)__cvta_generic_to_shared(p);
}

__device__ __forceinline__ void cp_async16(const void* smem_dst, const void* gsrc) {
    u32 sa = (u32)__cvta_generic_to_shared(smem_dst);
    asm volatile("cp.async.cg.shared.global [%0], [%1], 16;\n" :: "r"(sa), "l"(gsrc));
}
__device__ __forceinline__ void cp_commit() {
    asm volatile("cp.async.commit_group;\n");
}
__device__ __forceinline__ void cp_wait0() {
    asm volatile("cp.async.wait_group 0;\n");
}

// ---------------- kernels ----------------
__global__ void init_mm_kernel() {
    g_mm[0] = 0xFFFFFFFFu;
    g_mm[1] = 0u;
}

// fp32 -> bf16 bulk convert (rn)
__global__ void __launch_bounds__(256) conv_kernel(const float* __restrict__ src,
                                                   __nv_bfloat16* __restrict__ dst,
                                                   size_t n4) {
    for (size_t i = (size_t)blockIdx.x * blockDim.x + threadIdx.x; i < n4;
         i += (size_t)gridDim.x * blockDim.x) {
        float4 v = *reinterpret_cast<const float4*>(&src[i * 4]);
        __nv_bfloat162 lo = __floats2bfloat162_rn(v.x, v.y);
        __nv_bfloat162 hi = __floats2bfloat162_rn(v.z, v.w);
        *reinterpret_cast<__nv_bfloat162*>(&dst[i * 4]) = lo;
        *reinterpret_cast<__nv_bfloat162*>(&dst[i * 4 + 2]) = hi;
    }
}

// per-(iter,row) whale draws: A, C, spiral factor, mode (bit-identical math,
// relocated from whale_kernel). grid (32, NITER) x 256.
__global__ void __launch_bounds__(256) draw_kernel(KeyTab kt) {
    const int row = blockIdx.x * 256 + threadIdx.x;
    const int it = blockIdx.y;
    if (row >= NROWS) return;
    const float itf = (float)it;
    const float a = __fsub_rn(2.0f, __fmul_rn(itf, 0.2f));
    const float twoa = __fmul_rn(2.0f, a);
    const float a2m1 = __fsub_rn(__fadd_rn(-1.0f, __fmul_rn(itf, -0.1f)), 1.0f);
    const float r1 = bits01(dbits32(kt.k[it][0], kt.k[it][1], (u32)row));
    const float r2 = bits01(dbits32(kt.k[it][2], kt.k[it][3], (u32)row));
    const float u3 = bits01(dbits32(kt.k[it][4], kt.k[it][5], (u32)row));
    const float p  = bits01(dbits32(kt.k[it][6], kt.k[it][7], (u32)row));
    const float A  = __fsub_rn(__fmul_rn(twoa, r1), a);
    const float C  = 2.0f * r2;
    const float lp = __fadd_rn(__fmul_rn(a2m1, u3), 1.0f);
    const int mode = (p < 0.5f) ? ((fabsf(A) >= 1.0f) ? 0 : 1) : 2;
    const float sp = expf(lp) * cosf(6.283185307179586f * lp);
    g_draw[it * NROWS + row] = make_float4(A, C, sp, (float)mode);
}

// fill gather-index table for explore-mode (iter,row) pairs. grid NROWS x 128.
__global__ void __launch_bounds__(128) ridx_kernel(KeyTab kt) {
    const int row = blockIdx.x;
    const int t = threadIdx.x;
    for (int it = 0; it < NITER; it++) {
        if (__float2int_rn(g_draw[it * NROWS + row].w) != 0) continue;
        const u32 kba = kt.k[it][8], kbb = kt.k[it][9];
        u16* rp = &g_ridx[((size_t)it * NROWS + row) * DCOLS + t * 8];
        u16 v[8];
#pragma unroll
        for (int q = 0; q < 8; q++) {
            u32 m = (u32)row * 1024u + (u32)(t * 8 + q);
            v[q] = (u16)(dbits32(kba, kbb, m) & 8191u);
        }
        *reinterpret_cast<uint4*>(rp) = *reinterpret_cast<const uint4*>(v);
    }
}

// ---- GEMM1: round-15 proven (bf16, 128x128, BK=64, hoisted fragments) ----
__global__ void __launch_bounds__(256, 2) bf16_gemm1_kernel(
    const __nv_bfloat16* __restrict__ A, const __nv_bfloat16* __restrict__ B,
    const float* __restrict__ Caux,
    float* __restrict__ D0, float* __restrict__ D1,
    const float* __restrict__ scal)
{
    extern __shared__ __align__(16) u32 dsm[];
    u32* Asm = dsm;                    // [2][HA_STAGE]
    u32* Bsm = dsm + 2 * HA_STAGE;     // [2][HB_STAGE]
    __shared__ u32 redmin[8], redmax[8];

    const int tid = threadIdx.x;
    const int lane = tid & 31;
    const int warp = tid >> 5;
    const int wm = (warp & 1) * 64;
    const int wn = (warp >> 1) * 32;
    const int rowBase = blockIdx.y * 128;
    const int colBase = blockIdx.x * 128;
    const int lg = lane >> 2;
    const int lr = lane & 3;
    const int N = DCOLS, K = KDIM;

    const int arow = lane & 15;
    const int akoff = (lane >> 4) * 4;
    const int bg = lane >> 3;
    const int bgi = lane & 7;
    const u32 bloff = (u32)(((bg & 1) * 8 + bgi) * (HB_STRIDE * 4) + (wn + (bg >> 1) * 8) * 2);

    float acc[4][4][4];
#pragma unroll
    for (int mt = 0; mt < 4; mt++)
#pragma unroll
        for (int nt = 0; nt < 4; nt++)
#pragma unroll
            for (int r = 0; r < 4; r++) acc[mt][nt][r] = 0.0f;

#define CPA(S, K0)                                                             \
    {                                                                          \
        _Pragma("unroll")                                                      \
        for (int q = 0; q < 4; q++) {                                          \
            int ch = tid + 256 * q;                                            \
            int row = ch >> 3, cc = ch & 7;                                    \
            cp_async16(&Asm[(S) * HA_STAGE + row * HA_STRIDE + cc * 4],        \
                       &A[(size_t)(rowBase + row) * K + (K0) + cc * 8]);       \
        }                                                                      \
    }
#define CPB(S, K0)                                                             \
    {                                                                          \
        _Pragma("unroll")                                                      \
        for (int q = 0; q < 4; q++) {                                          \
            int ch = tid + 256 * q;                                            \
            int row = ch >> 4, cc = ch & 15;                                   \
            cp_async16(&Bsm[(S) * HB_STAGE + row * HB_STRIDE + cc * 4],        \
                       &B[(size_t)((K0) + row) * N + colBase + cc * 8]);       \
        }                                                                      \
    }

    CPA(0, 0)
    CPB(0, 0)
    cp_commit();

    int s = 0;
    const int T = K / HBK;   // 128
    for (int t = 0; t < T; t++, s ^= 1) {
        cp_wait0();
        __syncthreads();
        if (t + 1 < T) {
            CPA(s ^ 1, (t + 1) * HBK)
            CPB(s ^ 1, (t + 1) * HBK)
        }
        cp_commit();

        const u32 abase = smem_u32(&Asm[s * HA_STAGE + (wm + arow) * HA_STRIDE + akoff]);
        const u32 bbase = smem_u32(&Bsm[s * HB_STAGE]) + bloff;
#pragma unroll
        for (int ks = 0; ks < 4; ks++) {
            u32 af[4][4];
            u32 bf[4][2];
#pragma unroll
            for (int mt = 0; mt < 4; mt++)
                ldsm_x4(af[mt], abase + mt * (16 * HA_STRIDE * 4) + ks * 32);
#pragma unroll
            for (int ntp = 0; ntp < 2; ntp++) {
                u32 r[4];
                ldsm_x4_trans(r, bbase + (u32)(ks * 16 * HB_STRIDE * 4 + ntp * 32));
                bf[ntp * 2][0] = r[0];
                bf[ntp * 2][1] = r[1];
                bf[ntp * 2 + 1][0] = r[2];
                bf[ntp * 2 + 1][1] = r[3];
            }
#pragma unroll
            for (int mt = 0; mt < 4; mt++)
#pragma unroll
                for (int nt = 0; nt < 4; nt++)
                    mma_bf16(acc[mt][nt], af[mt], bf[nt]);
        }
    }

    const float alpha = *scal;
    const float oma = 1.0f - alpha;
    u32 lmin = 0xFFFFFFFFu, lmax = 0u;
#pragma unroll
    for (int mt = 0; mt < 4; mt++) {
#pragma unroll
        for (int nt = 0; nt < 4; nt++) {
            int row = rowBase + wm + mt * 16 + lg;
            int col = colBase + wn + nt * 8 + lr * 2;
            size_t off0 = (size_t)row * N + col;
            size_t off1 = off0 + (size_t)8 * N;
            float2 c0 = *reinterpret_cast<const float2*>(&Caux[off0]);
            float2 c1 = *reinterpret_cast<const float2*>(&Caux[off1]);
            float2 s0, s1;
            s0.x = oma * acc[mt][nt][0] + alpha * c0.x;
            s0.y = oma * acc[mt][nt][1] + alpha * c0.y;
            s1.x = oma * acc[mt][nt][2] + alpha * c1.x;
            s1.y = oma * acc[mt][nt][3] + alpha * c1.y;
            u32 q0 = f2key(s0.x), q1 = f2key(s0.y), q2 = f2key(s1.x), q3 = f2key(s1.y);
            lmin = min(min(min(q0, q1), min(q2, q3)), lmin);
            lmax = max(max(max(q0, q1), max(q2, q3)), lmax);
            *reinterpret_cast<float2*>(&D0[off0]) = s0;
            *reinterpret_cast<float2*>(&D0[off1]) = s1;
            *reinterpret_cast<float2*>(&D1[off0]) = s0;
            *reinterpret_cast<float2*>(&D1[off1]) = s1;
        }
    }
#pragma unroll
    for (int o = 16; o > 0; o >>= 1) {
        lmin = min(lmin, __shfl_xor_sync(0xffffffffu, lmin, o));
        lmax = max(lmax, __shfl_xor_sync(0xffffffffu, lmax, o));
    }
    if (lane == 0) { redmin[warp] = lmin; redmax[warp] = lmax; }
    __syncthreads();
    if (tid == 0) {
        u32 m0 = redmin[0], m1 = redmax[0];
#pragma unroll
        for (int q = 1; q < 8; q++) { m0 = min(m0, redmin[q]); m1 = max(m1, redmax[q]); }
        atomicMin(&g_mm[0], m0);
        atomicMax(&g_mm[1], m1);
    }
#undef CPA
#undef CPB
}

// ---- GEMM2: tf32, BK=32 (round-14 proven), mode-1 epilogue ----
__global__ void __launch_bounds__(256, 2) tf32_gemm2_kernel(
    const float* __restrict__ A, const float* __restrict__ B,
    int N, int K,
    const float* __restrict__ Caux,
    float* __restrict__ D0,
    const float* __restrict__ scal, const int* __restrict__ lptr)
{
    extern __shared__ __align__(16) float dsf[];
    float* As = dsf;
    float* Bs = dsf + 2 * G2AS_STAGE;

    const int tid = threadIdx.x;
    const int lane = tid & 31;
    const int warp = tid >> 5;
    const int wm = (warp & 1) * 64;
    const int wn = (warp >> 1) * 32;
    const int rowBase = blockIdx.y * 128;
    const int colBase = blockIdx.x * 128;
    const int lg = lane >> 2;
    const int lr = lane & 3;

    float acc[4][4][4];
#pragma unroll
    for (int mt = 0; mt < 4; mt++)
#pragma unroll
        for (int nt = 0; nt < 4; nt++)
#pragma unroll
            for (int r = 0; r < 4; r++) acc[mt][nt][r] = 0.0f;

#define LOAD_STAGE(S, K0)                                                        \
    {                                                                            \
        _Pragma("unroll")                                                        \
        for (int q = 0; q < 4; q++) {                                            \
            int ch = tid + 256 * q;                                              \
            int r = ch >> 3, cc = (ch & 7) << 2;                                 \
            cp_async16(&As[(S) * G2AS_STAGE + r * G2AS_STRIDE + cc],             \
                       &A[(size_t)(rowBase + r) * K + (K0) + cc]);               \
        }                                                                        \
        _Pragma("unroll")                                                        \
        for (int q = 0; q < 4; q++) {                                            \
            int ch = tid + 256 * q;                                              \
            int kk = ch >> 5, nn = (ch & 31) << 2;                               \
            cp_async16(&Bs[(S) * G2BS_STAGE + kk * G2BS_STRIDE + nn],            \
                       &B[(size_t)((K0) + kk) * N + colBase + nn]);              \
        }                                                                        \
        cp_commit();                                                             \
    }

    LOAD_STAGE(0, 0)
    int s = 0;
    for (int k0 = 0; k0 < K; k0 += G2BK) {
        cp_wait0();
        __syncthreads();
        if (k0 + G2BK < K) LOAD_STAGE(s ^ 1, k0 + G2BK)

        const float* __restrict__ as = &As[s * G2AS_STAGE];
        const float* __restrict__ bs = &Bs[s * G2BS_STAGE];
#pragma unroll
        for (int ks = 0; ks < 4; ks++) {
            const int kb = ks * 8;
            u32 af[4][4], bfr[4][2];
#pragma unroll
            for (int mt = 0; mt < 4; mt++) {
                int r0 = (wm + mt * 16 + lg) * G2AS_STRIDE + kb + lr;
                af[mt][0] = f2tf32(as[r0]);
                af[mt][1] = f2tf32(as[r0 + 8 * G2AS_STRIDE]);
                af[mt][2] = f2tf32(as[r0 + 4]);
                af[mt][3] = f2tf32(as[r0 + 8 * G2AS_STRIDE + 4]);
            }
#pragma unroll
            for (int nt = 0; nt < 4; nt++) {
                int c0 = (kb + lr) * G2BS_STRIDE + wn + nt * 8 + lg;
                bfr[nt][0] = f2tf32(bs[c0]);
                bfr[nt][1] = f2tf32(bs[c0 + 4 * G2BS_STRIDE]);
            }
#pragma unroll
            for (int mt = 0; mt < 4; mt++)
#pragma unroll
                for (int nt = 0; nt < 4; nt++)
                    mma_tf32(acc[mt][nt], af[mt], bfr[nt]);
        }
        s ^= 1;
    }
#undef LOAD_STAGE

    const float lam = *scal;
    const float lv = (float)(*lptr);
    const float theta = logf(lam / lv + 1.0f);
    const float omt = 1.0f - theta;
#pragma unroll
    for (int mt = 0; mt < 4; mt++) {
#pragma unroll
        for (int nt = 0; nt < 4; nt++) {
            int row = rowBase + wm + mt * 16 + lg;
            int col = colBase + wn + nt * 8 + lr * 2;
            size_t off0 = (size_t)row * N + col;
            size_t off1 = off0 + (size_t)8 * N;
            float2 c0 = *reinterpret_cast<const float2*>(&Caux[off0]);
            float2 c1 = *reinterpret_cast<const float2*>(&Caux[off1]);
            float2 s0, s1;
            s0.x = theta * acc[mt][nt][0] + omt * c0.x;
            s0.y = theta * acc[mt][nt][1] + omt * c0.y;
            s1.x = theta * acc[mt][nt][2] + omt * c1.x;
            s1.y = theta * acc[mt][nt][3] + omt * c1.y;
            *reinterpret_cast<float2*>(&D0[off0]) = s0;
            *reinterpret_cast<float2*>(&D0[off1]) = s1;
        }
    }
}

// whale: per-row draws + gather indices PRECOMPUTED; one block per row,
// 128 threads x 8 cols. No threefry / expf / cosf in the hot path.
__global__ void __launch_bounds__(128) whale_kernel(
    const float* __restrict__ posIn, float* __restrict__ posOut,
    int leaderIdx, int it)
{
    const int i = blockIdx.x;
    const int t = threadIdx.x;
    const int j0 = t * 8;
    const size_t base = (size_t)i * DCOLS + j0;
    const size_t lbase = (size_t)leaderIdx * DCOLS + j0;

    const float4 p0 = *reinterpret_cast<const float4*>(&posIn[base]);
    const float4 p1 = *reinterpret_cast<const float4*>(&posIn[base + 4]);
    const float4 l0 = *reinterpret_cast<const float4*>(&posIn[lbase]);
    const float4 l1 = *reinterpret_cast<const float4*>(&posIn[lbase + 4]);

    const float4 dr = __ldg(&g_draw[it * NROWS + i]);
    const float A = dr.x, C = dr.y, sp = dr.z;
    const int mode = __float2int_rn(dr.w);
    const float lower = key2f(g_mm[0]);
    const float upper = key2f(g_mm[1]);

    float pos[8] = {p0.x, p0.y, p0.z, p0.w, p1.x, p1.y, p1.z, p1.w};
    float led[8] = {l0.x, l0.y, l0.z, l0.w, l1.x, l1.y, l1.z, l1.w};
    float outv[8];

    if (mode == 0) {
        u16 r8[8];
        *reinterpret_cast<uint4*>(r8) = *reinterpret_cast<const uint4*>(
            &g_ridx[((size_t)it * NROWS + i) * DCOLS + j0]);
#pragma unroll
        for (int q = 0; q < 8; q++) {
            float xr = __ldg(&posIn[(size_t)r8[q] * DCOLS + j0 + q]);
            outv[q] = fabsf(xr - A * fabsf(C * xr - pos[q]));
        }
    } else if (mode == 1) {
#pragma unroll
        for (int q = 0; q < 8; q++)
            outv[q] = fabsf(led[q] - A * fabsf(C * led[q] - pos[q]));
    } else {
#pragma unroll
        for (int q = 0; q < 8; q++)
            outv[q] = fabsf(fabsf(led[q] - pos[q]) * sp + led[q]);
    }
    float4 o0, o1;
    o0.x = fminf(fmaxf(outv[0], lower), upper);
    o0.y = fminf(fmaxf(outv[1], lower), upper);
    o0.z = fminf(fmaxf(outv[2], lower), upper);
    o0.w = fminf(fmaxf(outv[3], lower), upper);
    o1.x = fminf(fmaxf(outv[4], lower), upper);
    o1.y = fminf(fmaxf(outv[5], lower), upper);
    o1.z = fminf(fmaxf(outv[6], lower), upper);
    o1.w = fminf(fmaxf(outv[7], lower), upper);
    *reinterpret_cast<float4*>(&posOut[base]) = o0;
    *reinterpret_cast<float4*>(&posOut[base + 4]) = o1;
}

// ---------------- host ----------------
extern "C" void kernel_launch(void* const* d_in, const int* in_sizes, int n_in,
                              void* d_out, int out_size) {
    (void)in_sizes; (void)n_in; (void)out_size;
    const float* input  = (const float*)d_in[0];
    const float* adj    = (const float*)d_in[1];
    const float* h0     = (const float*)d_in[2];
    const float* weight = (const float*)d_in[3];
    const float* lamda  = (const float*)d_in[4];
    const float* alpha  = (const float*)d_in[5];
    const int*   lint   = (const int*)d_in[6];
    float* out = (float*)d_out;

    float *support, *posA, *posB;
    __nv_bfloat16 *adj_bf, *in_bf;
    cudaGetSymbolAddress((void**)&support, g_support);
    cudaGetSymbolAddress((void**)&posA, g_posA);
    cudaGetSymbolAddress((void**)&posB, g_posB);
    cudaGetSymbolAddress((void**)&adj_bf, g_adj_bf);
    cudaGetSymbolAddress((void**)&in_bf, g_in_bf);

    cudaFuncSetAttribute(bf16_gemm1_kernel,
                         cudaFuncAttributeMaxDynamicSharedMemorySize, GEMM1_DSMEM);
    cudaFuncSetAttribute(tf32_gemm2_kernel,
                         cudaFuncAttributeMaxDynamicSharedMemorySize, GEMM2_DSMEM);

    // ---- JAX RNG derivation for key(42), partitionable-threefry semantics ----
    const u32 B0 = 0u, B1 = 42u;
    u32 K00, K01, L0, L1;
    htf(B0, B1, 0u, 0u, &K00, &K01);
    htf(B0, B1, 0u, 1u, &L0, &L1);
    u32 lka, lkb;
    htf(K00, K01, 0u, 1u, &lka, &lkb);
    int leader0 = (int)(hbits32(lka, lkb, 0u) & 8191u);

    KeyTab kt;
    int leaders[NITER];
    int leader = leader0;
    for (int it = 0; it < NITER; it++) {
        leaders[it] = leader;
        u32 f0, f1;
        htf(L0, L1, 0u, (u32)it, &f0, &f1);
        u32 SK[6][2];
        for (int j = 0; j < 6; j++) htf(f0, f1, 0u, (u32)j, &SK[j][0], &SK[j][1]);
        for (int j = 0; j < 4; j++) {
            kt.k[it][2 * j] = SK[j][0];
            kt.k[it][2 * j + 1] = SK[j][1];
        }
        u32 kba, kbb;
        htf(SK[4][0], SK[4][1], 0u, 1u, &kba, &kbb);
        kt.k[it][8] = kba;
        kt.k[it][9] = kbb;
        u32 l6a, l6b;
        htf(SK[5][0], SK[5][1], 0u, 1u, &l6a, &l6b);
        leader = (int)(hbits32(l6a, l6b, 0u) & 8191u);
    }

    init_mm_kernel<<<1, 1>>>();
    draw_kernel<<<dim3(32, NITER), 256>>>(kt);
    ridx_kernel<<<NROWS, 128>>>(kt);
    conv_kernel<<<2048, 256>>>(adj, adj_bf, (size_t)NROWS * KDIM / 4);
    conv_kernel<<<512, 256>>>(input, in_bf, (size_t)NROWS * DCOLS / 4);

    // GEMM1 (bf16): support/posA = (1-alpha)*(adj@input) + alpha*h0, + min/max
    dim3 g1(DCOLS / 128, NROWS / 128);
    bf16_gemm1_kernel<<<g1, 256, GEMM1_DSMEM>>>(adj_bf, in_bf, h0, support, posA, alpha);

    float* pin = posA;
    float* pout = posB;
    for (int it = 0; it < NITER; it++) {
        whale_kernel<<<NROWS, 128>>>(pin, pout, leaders[it], it);
        float* tswap = pin; pin = pout; pout = tswap;
    }

    // GEMM2 (tf32): out = theta*(pos@weight) + (1-theta)*support
    dim3 g2(DCOLS / 128, NROWS / 128);
    tf32_gemm2_kernel<<<g2, 256, GEMM2_DSMEM>>>(pin, weight, DCOLS, DCOLS,
                                                support, out, lamda, lint);
}

// round 17
// speedup vs baseline: 1.0589x; 1.0589x over previous
#include <cuda_runtime.h>
#include <cuda_bf16.h>
#include <cstdint>
#include <math.h>

typedef unsigned int u32;

#define NROWS 8192
#define DCOLS 1024
#define KDIM  8192
#define NITER 10

// tf32 GEMM (GEMM2): BK=32, dynamic smem (round-14 proven)
#define G2BK 32
#define G2AS_STRIDE 36
#define G2AS_STAGE (128 * G2AS_STRIDE)
#define G2BS_STRIDE 136
#define G2BS_STAGE (G2BK * G2BS_STRIDE)
#define GEMM2_DSMEM ((G2AS_STAGE + G2BS_STAGE) * 2 * 4)   // 71680 B

// bf16 GEMM (GEMM1): BK=64, 2-stage (round-15 proven, hoisted fragments)
#define HBK 64
#define HA_STRIDE 36
#define HA_STAGE (128 * HA_STRIDE)
#define HB_STRIDE 68
#define HB_STAGE (64 * HB_STRIDE)
#define GEMM1_DSMEM ((2 * HA_STAGE + 2 * HB_STAGE) * 4)   // 71680 B

// combined convert: adj is 2048 block-units of 4096 float4s, input is 512
#define CONV_ADJ_BLOCKS 2048
#define CONV_ALL_BLOCKS 2560

// ---------------- scratch (static __device__, no allocation) ----------------
__device__ float g_support[(size_t)NROWS * DCOLS];
__device__ float g_posA[(size_t)NROWS * DCOLS];
__device__ float g_posB[(size_t)NROWS * DCOLS];
__device__ __nv_bfloat16 g_adj_bf[(size_t)NROWS * KDIM];
__device__ __nv_bfloat16 g_in_bf[(size_t)NROWS * DCOLS];
__device__ unsigned g_mm[2];

// ---------------- threefry2x32 (JAX-exact) ----------------
__device__ __forceinline__ void dtf(u32 k0, u32 k1, u32 x0, u32 x1, u32& o0, u32& o1) {
    u32 ks2 = k0 ^ k1 ^ 0x1BD11BDAu;
    x0 += k0; x1 += k1;
#define TFROUND(r) { x0 += x1; x1 = __funnelshift_l(x1, x1, (r)); x1 ^= x0; }
    TFROUND(13) TFROUND(15) TFROUND(26) TFROUND(6)
    x0 += k1;  x1 += ks2 + 1u;
    TFROUND(17) TFROUND(29) TFROUND(16) TFROUND(24)
    x0 += ks2; x1 += k0 + 2u;
    TFROUND(13) TFROUND(15) TFROUND(26) TFROUND(6)
    x0 += k0;  x1 += k1 + 3u;
    TFROUND(17) TFROUND(29) TFROUND(16) TFROUND(24)
    x0 += k1;  x1 += ks2 + 4u;
    TFROUND(13) TFROUND(15) TFROUND(26) TFROUND(6)
    x0 += ks2; x1 += k0 + 5u;
#undef TFROUND
    o0 = x0; o1 = x1;
}

static void htf(u32 k0, u32 k1, u32 x0, u32 x1, u32* o0, u32* o1) {
    u32 ks[3] = {k0, k1, k0 ^ k1 ^ 0x1BD11BDAu};
    static const int R0[4] = {13, 15, 26, 6};
    static const int R1[4] = {17, 29, 16, 24};
    x0 += ks[0]; x1 += ks[1];
    for (int i = 0; i < 5; i++) {
        const int* R = (i & 1) ? R1 : R0;
        for (int j = 0; j < 4; j++) {
            x0 += x1;
            x1 = (x1 << R[j]) | (x1 >> (32 - R[j]));
            x1 ^= x0;
        }
        x0 += ks[(i + 1) % 3];
        x1 += ks[(i + 2) % 3] + (u32)(i + 1);
    }
    *o0 = x0; *o1 = x1;
}

__device__ __forceinline__ u32 dbits32(u32 k0, u32 k1, u32 e) {
    u32 o0, o1;
    dtf(k0, k1, 0u, e, o0, o1);
    return o0 ^ o1;
}
static u32 hbits32(u32 k0, u32 k1, u32 e) {
    u32 o0, o1;
    htf(k0, k1, 0u, e, &o0, &o1);
    return o0 ^ o1;
}

__device__ __forceinline__ float bits01(u32 b) {
    return __uint_as_float((b >> 9) | 0x3f800000u) - 1.0f;
}

__device__ __forceinline__ u32 f2key(float f) {
    u32 b = __float_as_uint(f);
    return (b & 0x80000000u) ? ~b : (b | 0x80000000u);
}
__device__ __forceinline__ float key2f(u32 k) {
    return __uint_as_float((k & 0x80000000u) ? (k ^ 0x80000000u) : ~k);
}

// ---------------- mma / cp.async helpers ----------------
__device__ __forceinline__ u32 f2tf32(float x) {
    u32 r;
    asm("cvt.rna.tf32.f32 %0, %1;" : "=r"(r) : "f"(x));
    return r;
}

__device__ __forceinline__ void mma_tf32(float* d, const u32* a, const u32* b) {
    asm volatile(
        "mma.sync.aligned.m16n8k8.row.col.f32.tf32.tf32.f32 "
        "{%0,%1,%2,%3}, {%4,%5,%6,%7}, {%8,%9}, {%0,%1,%2,%3};"
        : "+f"(d[0]), "+f"(d[1]), "+f"(d[2]), "+f"(d[3])
        : "r"(a[0]), "r"(a[1]), "r"(a[2]), "r"(a[3]), "r"(b[0]), "r"(b[1]));
}

__device__ __forceinline__ void mma_bf16(float* d, const u32* a, const u32* b) {
    asm volatile(
        "mma.sync.aligned.m16n8k16.row.col.f32.bf16.bf16.f32 "
        "{%0,%1,%2,%3}, {%4,%5,%6,%7}, {%8,%9}, {%0,%1,%2,%3};"
        : "+f"(d[0]), "+f"(d[1]), "+f"(d[2]), "+f"(d[3])
        : "r"(a[0]), "r"(a[1]), "r"(a[2]), "r"(a[3]), "r"(b[0]), "r"(b[1]));
}

__device__ __forceinline__ void ldsm_x4(u32* d, u32 saddr) {
    asm volatile(
        "ldmatrix.sync.aligned.m8n8.x4.shared.b16 {%0,%1,%2,%3}, [%4];"
        : "=r"(d[0]), "=r"(d[1]), "=r"(d[2]), "=r"(d[3]) : "r"(saddr));
}

__device__ __forceinline__ void ldsm_x4_trans(u32* d, u32 saddr) {
    asm volatile(
        "ldmatrix.sync.aligned.m8n8.x4.trans.shared.b16 {%0,%1,%2,%3}, [%4];"
        : "=r"(d[0]), "=r"(d[1]), "=r"(d[2]), "=r"(d[3]) : "r"(saddr));
}

__device__ __forceinline__ u32 smem_u32(const void* p) {
    return (u32)__cvta_generic_to_shared(p);
}

__device__ __forceinline__ void cp_async16(const void* smem_dst, const void* gsrc) {
    u32 sa = (u32)__cvta_generic_to_shared(smem_dst);
    asm volatile("cp.async.cg.shared.global [%0], [%1], 16;\n" :: "r"(sa), "l"(gsrc));
}
__device__ __forceinline__ void cp_commit() {
    asm volatile("cp.async.commit_group;\n");
}
__device__ __forceinline__ void cp_wait0() {
    asm volatile("cp.async.wait_group 0;\n");
}

// ---------------- kernels ----------------
__global__ void init_mm_kernel() {
    g_mm[0] = 0xFFFFFFFFu;
    g_mm[1] = 0u;
}

// fp32 -> bf16 bulk convert for BOTH adj and input in one launch.
// Blocks [0, CONV_ADJ_BLOCKS) handle adj; the rest handle input.
__global__ void __launch_bounds__(256) conv_all_kernel(const float* __restrict__ adj,
                                                       const float* __restrict__ input) {
    const bool isAdj = blockIdx.x < CONV_ADJ_BLOCKS;
    const float* src = isAdj ? adj : input;
    __nv_bfloat16* dst = isAdj ? g_adj_bf : g_in_bf;
    const size_t n4 = isAdj ? ((size_t)NROWS * KDIM / 4) : ((size_t)NROWS * DCOLS / 4);
    const size_t b0 = isAdj ? (size_t)blockIdx.x : (size_t)(blockIdx.x - CONV_ADJ_BLOCKS);
    const size_t nb = isAdj ? CONV_ADJ_BLOCKS : (CONV_ALL_BLOCKS - CONV_ADJ_BLOCKS);
    for (size_t i = b0 * blockDim.x + threadIdx.x; i < n4; i += nb * blockDim.x) {
        float4 v = *reinterpret_cast<const float4*>(&src[i * 4]);
        __nv_bfloat162 lo = __floats2bfloat162_rn(v.x, v.y);
        __nv_bfloat162 hi = __floats2bfloat162_rn(v.z, v.w);
        *reinterpret_cast<__nv_bfloat162*>(&dst[i * 4]) = lo;
        *reinterpret_cast<__nv_bfloat162*>(&dst[i * 4 + 2]) = hi;
    }
}

// ---- GEMM1: round-15 proven (bf16, 128x128, BK=64, hoisted fragments) ----
// Single output D0 = (1-alpha)*acc + alpha*h0 (whale it0 reads it directly);
// fused global min/max of result.
__global__ void __launch_bounds__(256, 2) bf16_gemm1_kernel(
    const __nv_bfloat16* __restrict__ A, const __nv_bfloat16* __restrict__ B,
    const float* __restrict__ Caux,
    float* __restrict__ D0,
    const float* __restrict__ scal)
{
    extern __shared__ __align__(16) u32 dsm[];
    u32* Asm = dsm;                    // [2][HA_STAGE]
    u32* Bsm = dsm + 2 * HA_STAGE;     // [2][HB_STAGE]
    __shared__ u32 redmin[8], redmax[8];

    const int tid = threadIdx.x;
    const int lane = tid & 31;
    const int warp = tid >> 5;
    const int wm = (warp & 1) * 64;
    const int wn = (warp >> 1) * 32;
    const int rowBase = blockIdx.y * 128;
    const int colBase = blockIdx.x * 128;
    const int lg = lane >> 2;
    const int lr = lane & 3;
    const int N = DCOLS, K = KDIM;

    const int arow = lane & 15;
    const int akoff = (lane >> 4) * 4;
    const int bg = lane >> 3;
    const int bgi = lane & 7;
    const u32 bloff = (u32)(((bg & 1) * 8 + bgi) * (HB_STRIDE * 4) + (wn + (bg >> 1) * 8) * 2);

    float acc[4][4][4];
#pragma unroll
    for (int mt = 0; mt < 4; mt++)
#pragma unroll
        for (int nt = 0; nt < 4; nt++)
#pragma unroll
            for (int r = 0; r < 4; r++) acc[mt][nt][r] = 0.0f;

#define CPA(S, K0)                                                             \
    {                                                                          \
        _Pragma("unroll")                                                      \
        for (int q = 0; q < 4; q++) {                                          \
            int ch = tid + 256 * q;                                            \
            int row = ch >> 3, cc = ch & 7;                                    \
            cp_async16(&Asm[(S) * HA_STAGE + row * HA_STRIDE + cc * 4],        \
                       &A[(size_t)(rowBase + row) * K + (K0) + cc * 8]);       \
        }                                                                      \
    }
#define CPB(S, K0)                                                             \
    {                                                                          \
        _Pragma("unroll")                                                      \
        for (int q = 0; q < 4; q++) {                                          \
            int ch = tid + 256 * q;                                            \
            int row = ch >> 4, cc = ch & 15;                                   \
            cp_async16(&Bsm[(S) * HB_STAGE + row * HB_STRIDE + cc * 4],        \
                       &B[(size_t)((K0) + row) * N + colBase + cc * 8]);       \
        }                                                                      \
    }

    CPA(0, 0)
    CPB(0, 0)
    cp_commit();

    int s = 0;
    const int T = K / HBK;   // 128
    for (int t = 0; t < T; t++, s ^= 1) {
        cp_wait0();
        __syncthreads();
        if (t + 1 < T) {
            CPA(s ^ 1, (t + 1) * HBK)
            CPB(s ^ 1, (t + 1) * HBK)
        }
        cp_commit();

        const u32 abase = smem_u32(&Asm[s * HA_STAGE + (wm + arow) * HA_STRIDE + akoff]);
        const u32 bbase = smem_u32(&Bsm[s * HB_STAGE]) + bloff;
#pragma unroll
        for (int ks = 0; ks < 4; ks++) {
            u32 af[4][4];
            u32 bf[4][2];
#pragma unroll
            for (int mt = 0; mt < 4; mt++)
                ldsm_x4(af[mt], abase + mt * (16 * HA_STRIDE * 4) + ks * 32);
#pragma unroll
            for (int ntp = 0; ntp < 2; ntp++) {
                u32 r[4];
                ldsm_x4_trans(r, bbase + (u32)(ks * 16 * HB_STRIDE * 4 + ntp * 32));
                bf[ntp * 2][0] = r[0];
                bf[ntp * 2][1] = r[1];
                bf[ntp * 2 + 1][0] = r[2];
                bf[ntp * 2 + 1][1] = r[3];
            }
#pragma unroll
            for (int mt = 0; mt < 4; mt++)
#pragma unroll
                for (int nt = 0; nt < 4; nt++)
                    mma_bf16(acc[mt][nt], af[mt], bf[nt]);
        }
    }

    const float alpha = *scal;
    const float oma = 1.0f - alpha;
    u32 lmin = 0xFFFFFFFFu, lmax = 0u;
#pragma unroll
    for (int mt = 0; mt < 4; mt++) {
#pragma unroll
        for (int nt = 0; nt < 4; nt++) {
            int row = rowBase + wm + mt * 16 + lg;
            int col = colBase + wn + nt * 8 + lr * 2;
            size_t off0 = (size_t)row * N + col;
            size_t off1 = off0 + (size_t)8 * N;
            float2 c0 = *reinterpret_cast<const float2*>(&Caux[off0]);
            float2 c1 = *reinterpret_cast<const float2*>(&Caux[off1]);
            float2 s0, s1;
            s0.x = oma * acc[mt][nt][0] + alpha * c0.x;
            s0.y = oma * acc[mt][nt][1] + alpha * c0.y;
            s1.x = oma * acc[mt][nt][2] + alpha * c1.x;
            s1.y = oma * acc[mt][nt][3] + alpha * c1.y;
            u32 q0 = f2key(s0.x), q1 = f2key(s0.y), q2 = f2key(s1.x), q3 = f2key(s1.y);
            lmin = min(min(min(q0, q1), min(q2, q3)), lmin);
            lmax = max(max(max(q0, q1), max(q2, q3)), lmax);
            *reinterpret_cast<float2*>(&D0[off0]) = s0;
            *reinterpret_cast<float2*>(&D0[off1]) = s1;
        }
    }
#pragma unroll
    for (int o = 16; o > 0; o >>= 1) {
        lmin = min(lmin, __shfl_xor_sync(0xffffffffu, lmin, o));
        lmax = max(lmax, __shfl_xor_sync(0xffffffffu, lmax, o));
    }
    if (lane == 0) { redmin[warp] = lmin; redmax[warp] = lmax; }
    __syncthreads();
    if (tid == 0) {
        u32 m0 = redmin[0], m1 = redmax[0];
#pragma unroll
        for (int q = 1; q < 8; q++) { m0 = min(m0, redmin[q]); m1 = max(m1, redmax[q]); }
        atomicMin(&g_mm[0], m0);
        atomicMax(&g_mm[1], m1);
    }
#undef CPA
#undef CPB
}

// ---- GEMM2: tf32, BK=32 (round-14 proven), mode-1 epilogue ----
__global__ void __launch_bounds__(256, 2) tf32_gemm2_kernel(
    const float* __restrict__ A, const float* __restrict__ B,
    int N, int K,
    const float* __restrict__ Caux,
    float* __restrict__ D0,
    const float* __restrict__ scal, const int* __restrict__ lptr)
{
    extern __shared__ __align__(16) float dsf[];
    float* As = dsf;
    float* Bs = dsf + 2 * G2AS_STAGE;

    const int tid = threadIdx.x;
    const int lane = tid & 31;
    const int warp = tid >> 5;
    const int wm = (warp & 1) * 64;
    const int wn = (warp >> 1) * 32;
    const int rowBase = blockIdx.y * 128;
    const int colBase = blockIdx.x * 128;
    const int lg = lane >> 2;
    const int lr = lane & 3;

    float acc[4][4][4];
#pragma unroll
    for (int mt = 0; mt < 4; mt++)
#pragma unroll
        for (int nt = 0; nt < 4; nt++)
#pragma unroll
            for (int r = 0; r < 4; r++) acc[mt][nt][r] = 0.0f;

#define LOAD_STAGE(S, K0)                                                        \
    {                                                                            \
        _Pragma("unroll")                                                        \
        for (int q = 0; q < 4; q++) {                                            \
            int ch = tid + 256 * q;                                              \
            int r = ch >> 3, cc = (ch & 7) << 2;                                 \
            cp_async16(&As[(S) * G2AS_STAGE + r * G2AS_STRIDE + cc],             \
                       &A[(size_t)(rowBase + r) * K + (K0) + cc]);               \
        }                                                                        \
        _Pragma("unroll")                                                        \
        for (int q = 0; q < 4; q++) {                                            \
            int ch = tid + 256 * q;                                              \
            int kk = ch >> 5, nn = (ch & 31) << 2;                               \
            cp_async16(&Bs[(S) * G2BS_STAGE + kk * G2BS_STRIDE + nn],            \
                       &B[(size_t)((K0) + kk) * N + colBase + nn]);              \
        }                                                                        \
        cp_commit();                                                             \
    }

    LOAD_STAGE(0, 0)
    int s = 0;
    for (int k0 = 0; k0 < K; k0 += G2BK) {
        cp_wait0();
        __syncthreads();
        if (k0 + G2BK < K) LOAD_STAGE(s ^ 1, k0 + G2BK)

        const float* __restrict__ as = &As[s * G2AS_STAGE];
        const float* __restrict__ bs = &Bs[s * G2BS_STAGE];
#pragma unroll
        for (int ks = 0; ks < 4; ks++) {
            const int kb = ks * 8;
            u32 af[4][4], bfr[4][2];
#pragma unroll
            for (int mt = 0; mt < 4; mt++) {
                int r0 = (wm + mt * 16 + lg) * G2AS_STRIDE + kb + lr;
                af[mt][0] = f2tf32(as[r0]);
                af[mt][1] = f2tf32(as[r0 + 8 * G2AS_STRIDE]);
                af[mt][2] = f2tf32(as[r0 + 4]);
                af[mt][3] = f2tf32(as[r0 + 8 * G2AS_STRIDE + 4]);
            }
#pragma unroll
            for (int nt = 0; nt < 4; nt++) {
                int c0 = (kb + lr) * G2BS_STRIDE + wn + nt * 8 + lg;
                bfr[nt][0] = f2tf32(bs[c0]);
                bfr[nt][1] = f2tf32(bs[c0 + 4 * G2BS_STRIDE]);
            }
#pragma unroll
            for (int mt = 0; mt < 4; mt++)
#pragma unroll
                for (int nt = 0; nt < 4; nt++)
                    mma_tf32(acc[mt][nt], af[mt], bfr[nt]);
        }
        s ^= 1;
    }
#undef LOAD_STAGE

    const float lam = *scal;
    const float lv = (float)(*lptr);
    const float theta = logf(lam / lv + 1.0f);
    const float omt = 1.0f - theta;
#pragma unroll
    for (int mt = 0; mt < 4; mt++) {
#pragma unroll
        for (int nt = 0; nt < 4; nt++) {
            int row = rowBase + wm + mt * 16 + lg;
            int col = colBase + wn + nt * 8 + lr * 2;
            size_t off0 = (size_t)row * N + col;
            size_t off1 = off0 + (size_t)8 * N;
            float2 c0 = *reinterpret_cast<const float2*>(&Caux[off0]);
            float2 c1 = *reinterpret_cast<const float2*>(&Caux[off1]);
            float2 s0, s1;
            s0.x = theta * acc[mt][nt][0] + omt * c0.x;
            s0.y = theta * acc[mt][nt][1] + omt * c0.y;
            s1.x = theta * acc[mt][nt][2] + omt * c1.x;
            s1.y = theta * acc[mt][nt][3] + omt * c1.y;
            *reinterpret_cast<float2*>(&D0[off0]) = s0;
            *reinterpret_cast<float2*>(&D0[off1]) = s1;
        }
    }
}

// one block per agent row; 128 threads x 8 cols (ROUND-10 proven version)
__global__ void __launch_bounds__(128) whale_kernel(
    const float* __restrict__ posIn, float* __restrict__ posOut,
    int leaderIdx, float av, float twoa, float a2m1,
    u32 k1a, u32 k1b, u32 k2a, u32 k2b, u32 k3a, u32 k3b, u32 k4a, u32 k4b,
    u32 kba, u32 kbb)
{
    const int i = blockIdx.x;
    const int t = threadIdx.x;
    const int lane = t & 31;
    const int j0 = t * 8;
    const size_t base = (size_t)i * DCOLS + j0;
    const size_t lbase = (size_t)leaderIdx * DCOLS + j0;

    const float4 p0 = *reinterpret_cast<const float4*>(&posIn[base]);
    const float4 p1 = *reinterpret_cast<const float4*>(&posIn[base + 4]);
    const float4 l0 = *reinterpret_cast<const float4*>(&posIn[lbase]);
    const float4 l1 = *reinterpret_cast<const float4*>(&posIn[lbase + 4]);

    const int sel = lane & 3;
    u32 ka = (sel == 0) ? k1a : (sel == 1) ? k2a : (sel == 2) ? k3a : k4a;
    u32 kb = (sel == 0) ? k1b : (sel == 1) ? k2b : (sel == 2) ? k3b : k4b;
    float rv = bits01(dbits32(ka, kb, (u32)i));
    const float r1 = __shfl_sync(0xffffffffu, rv, 0);
    const float r2 = __shfl_sync(0xffffffffu, rv, 1);
    const float u3 = __shfl_sync(0xffffffffu, rv, 2);
    const float p  = __shfl_sync(0xffffffffu, rv, 3);

    const float A  = __fsub_rn(__fmul_rn(twoa, r1), av);
    const float C  = 2.0f * r2;
    const float lp = __fadd_rn(__fmul_rn(a2m1, u3), 1.0f);
    const float lower = key2f(g_mm[0]);
    const float upper = key2f(g_mm[1]);
    const int mode = (p < 0.5f) ? ((fabsf(A) >= 1.0f) ? 0 : 1) : 2;

    float pos[8] = {p0.x, p0.y, p0.z, p0.w, p1.x, p1.y, p1.z, p1.w};
    float led[8] = {l0.x, l0.y, l0.z, l0.w, l1.x, l1.y, l1.z, l1.w};
    float outv[8];

    if (mode == 0) {
#pragma unroll
        for (int q = 0; q < 8; q++) {
            u32 m = (u32)i * 1024u + (u32)(j0 + q);
            u32 bits = dbits32(kba, kbb, m);
            int ridx = (int)(bits & 8191u);
            float xr = __ldg(&posIn[(size_t)ridx * DCOLS + j0 + q]);
            outv[q] = fabsf(xr - A * fabsf(C * xr - pos[q]));
        }
    } else if (mode == 1) {
#pragma unroll
        for (int q = 0; q < 8; q++)
            outv[q] = fabsf(led[q] - A * fabsf(C * led[q] - pos[q]));
    } else {
        const float sp = expf(lp) * cosf(6.283185307179586f * lp);
#pragma unroll
        for (int q = 0; q < 8; q++)
            outv[q] = fabsf(fabsf(led[q] - pos[q]) * sp + led[q]);
    }
    float4 o0, o1;
    o0.x = fminf(fmaxf(outv[0], lower), upper);
    o0.y = fminf(fmaxf(outv[1], lower), upper);
    o0.z = fminf(fmaxf(outv[2], lower), upper);
    o0.w = fminf(fmaxf(outv[3], lower), upper);
    o1.x = fminf(fmaxf(outv[4], lower), upper);
    o1.y = fminf(fmaxf(outv[5], lower), upper);
    o1.z = fminf(fmaxf(outv[6], lower), upper);
    o1.w = fminf(fmaxf(outv[7], lower), upper);
    *reinterpret_cast<float4*>(&posOut[base]) = o0;
    *reinterpret_cast<float4*>(&posOut[base + 4]) = o1;
}

// ---------------- host ----------------
extern "C" void kernel_launch(void* const* d_in, const int* in_sizes, int n_in,
                              void* d_out, int out_size) {
    (void)in_sizes; (void)n_in; (void)out_size;
    const float* input  = (const float*)d_in[0];
    const float* adj    = (const float*)d_in[1];
    const float* h0     = (const float*)d_in[2];
    const float* weight = (const float*)d_in[3];
    const float* lamda  = (const float*)d_in[4];
    const float* alpha  = (const float*)d_in[5];
    const int*   lint   = (const int*)d_in[6];
    float* out = (float*)d_out;

    float *support, *posA, *posB;
    __nv_bfloat16 *adj_bf, *in_bf;
    cudaGetSymbolAddress((void**)&support, g_support);
    cudaGetSymbolAddress((void**)&posA, g_posA);
    cudaGetSymbolAddress((void**)&posB, g_posB);
    cudaGetSymbolAddress((void**)&adj_bf, g_adj_bf);
    cudaGetSymbolAddress((void**)&in_bf, g_in_bf);

    cudaFuncSetAttribute(bf16_gemm1_kernel,
                         cudaFuncAttributeMaxDynamicSharedMemorySize, GEMM1_DSMEM);
    cudaFuncSetAttribute(tf32_gemm2_kernel,
                         cudaFuncAttributeMaxDynamicSharedMemorySize, GEMM2_DSMEM);

    init_mm_kernel<<<1, 1>>>();
    conv_all_kernel<<<CONV_ALL_BLOCKS, 256>>>(adj, input);

    // GEMM1 (bf16): support = (1-alpha)*(adj@input) + alpha*h0, + fused min/max
    dim3 g1(DCOLS / 128, NROWS / 128);
    bf16_gemm1_kernel<<<g1, 256, GEMM1_DSMEM>>>(adj_bf, in_bf, h0, support, alpha);

    // ---- JAX RNG derivation for key(42), partitionable-threefry semantics ----
    const u32 B0 = 0u, B1 = 42u;
    u32 K00, K01, L0, L1;
    htf(B0, B1, 0u, 0u, &K00, &K01);
    htf(B0, B1, 0u, 1u, &L0, &L1);
    u32 lka, lkb;
    htf(K00, K01, 0u, 1u, &lka, &lkb);
    int leader = (int)(hbits32(lka, lkb, 0u) & 8191u);

    // whale it0 reads support directly (identical values to old posA copy)
    const float* pin = support;
    float* pout = posA;
    for (int it = 0; it < NITER; it++) {
        u32 f0, f1;
        htf(L0, L1, 0u, (u32)it, &f0, &f1);
        u32 SK[6][2];
        for (int j = 0; j < 6; j++) htf(f0, f1, 0u, (u32)j, &SK[j][0], &SK[j][1]);
        u32 k5a = SK[4][0], k5b = SK[4][1];
        u32 k6a = SK[5][0], k6b = SK[5][1];
        u32 kba, kbb;
        htf(k5a, k5b, 0u, 1u, &kba, &kbb);
        u32 l6a, l6b;
        htf(k6a, k6b, 0u, 1u, &l6a, &l6b);
        int nextLeader = (int)(hbits32(l6a, l6b, 0u) & 8191u);

        const float itf = (float)it;
        volatile float tmul = itf * 0.2f;
        const float a = 2.0f - tmul;
        const float twoa = 2.0f * a;
        volatile float tmul2 = itf * (-0.1f);
        const float a2 = -1.0f + tmul2;
        const float a2m1 = a2 - 1.0f;

        whale_kernel<<<NROWS, 128>>>(pin, pout, leader, a, twoa, a2m1,
                                     SK[0][0], SK[0][1], SK[1][0], SK[1][1],
                                     SK[2][0], SK[2][1], SK[3][0], SK[3][1],
                                     kba, kbb);
        leader = nextLeader;
        // chain: support -> posA -> posB -> posA -> ... (it9 writes posB)
        pin = pout;
        pout = (pout == posA) ? posB : posA;
    }
    // after 10 iters final positions are in posB (pin points at it)

    // GEMM2 (tf32): out = theta*(pos@weight) + (1-theta)*support
    dim3 g2(DCOLS / 128, NROWS / 128);
    tf32_gemm2_kernel<<<g2, 256, GEMM2_DSMEM>>>(pin, weight, DCOLS, DCOLS,
                                                support, out, lamda, lint);
}